// round 16
// baseline (speedup 1.0000x reference)
#include <cuda_runtime.h>
#include <cstdint>

#define BB 16
#define TT 512
#define DD 384
#define OUT_LEN 3584            // T * (MAX_DUR - 1)
#define ROWS 32                 // output rows per block (2 per warp)
#define BLOCKS_PER_B (OUT_LEN / ROWS)   // 112
#define NT 512                  // 16 warps
#define V4 (DD / 4)             // 96 float4 per row

// R15 design with 2x amortized prologue: NT=512/ROWS=32 keeps 64 warps/SM
// (4 CTAs x 512) while halving per-row scan cost.
__global__ void __launch_bounds__(NT, 4)
lr_fused(const float* __restrict__ xs, const int* __restrict__ ds,
         const int* __restrict__ ilens, float* __restrict__ out) {
    __shared__ int csum[TT];
    __shared__ int wtot[16];
    __shared__ int srcs[ROWS];

    const int tid = threadIdx.x;
    const int lane = tid & 31;
    const int w = tid >> 5;               // 16 warps
    const int b = blockIdx.y;
    const int r0 = blockIdx.x * ROWS;

    // ---- masked duration load: 1 per thread ----
    const int ilen = __ldg(ilens + b);
    int d = ds[b * TT + tid];
    d = (tid < ilen) ? d : 0;

    // ---- block inclusive scan -> csum ----
    int x = d;
    #pragma unroll
    for (int off = 1; off < 32; off <<= 1) {
        int y = __shfl_up_sync(0xFFFFFFFFu, x, off);
        if (lane >= off) x += y;
    }
    if (lane == 31) wtot[w] = x;
    __syncthreads();
    if (w == 0) {
        int v = (lane < 16) ? wtot[lane] : 0;
        #pragma unroll
        for (int off = 1; off < 16; off <<= 1) {
            int y = __shfl_up_sync(0xFFFFFFFFu, v, off);
            if (lane >= off) v += y;
        }
        if (lane < 16) wtot[lane] = v;     // inclusive warp totals
    }
    __syncthreads();
    const int incl = x + ((w > 0) ? wtot[w - 1] : 0);
    csum[tid] = incl;
    __syncthreads();

    const int total = csum[TT - 1];
    const int p = min(max(total - r0, 0), ROWS);   // valid rows are a prefix

    // ---- searchsorted(csum, t, 'right'): 10 halvings for [0,512] ----
    if (tid < ROWS) {
        int s = -1;
        if (tid < p) {
            const int t = r0 + tid;
            int lo = 0, hi = TT;
            #pragma unroll
            for (int it = 0; it < 10; ++it) {
                int mid = (lo + hi) >> 1;
                if (csum[mid] <= t) lo = mid + 1; else hi = mid;
            }
            s = lo;
        }
        srcs[tid] = s;
    }
    __syncthreads();

    // ---- warp-per-row gather: warp w handles rows 2w, 2w+1 ----
    const float4* __restrict__ xb = (const float4*)xs + (size_t)b * TT * V4;
    float4* __restrict__ ob = (float4*)out + ((size_t)b * OUT_LEN + r0) * V4;

    const int ra = 2 * w;
    const int rb = ra + 1;
    const int sa = srcs[ra];              // broadcast LDS
    const int sb = srcs[rb];

    const float4 zero = make_float4(0.f, 0.f, 0.f, 0.f);
    float4 va0 = zero, va1 = zero, va2 = zero;
    float4 vb0 = zero, vb1 = zero, vb2 = zero;

    // Batch all 6 loads (warp-uniform predicates, MLP=6).
    if (sa >= 0) {
        const float4* sra = xb + sa * V4 + lane;
        va0 = sra[0]; va1 = sra[32]; va2 = sra[64];
    }
    if (sb >= 0) {
        const float4* srb = xb + sb * V4 + lane;
        vb0 = srb[0]; vb1 = srb[32]; vb2 = srb[64];
    }

    // 6 coalesced evict-first STG.128.
    float4* da = ob + ra * V4 + lane;
    float4* db = ob + rb * V4 + lane;
    __stcs(da,      va0); __stcs(da + 32, va1); __stcs(da + 64, va2);
    __stcs(db,      vb0); __stcs(db + 32, vb1); __stcs(db + 64, vb2);
}

extern "C" void kernel_launch(void* const* d_in, const int* in_sizes, int n_in,
                              void* d_out, int out_size) {
    const float* xs = (const float*)d_in[0];
    const int* ds = (const int*)d_in[1];
    const int* ilens = (const int*)d_in[2];
    float* out = (float*)d_out;

    dim3 grid(BLOCKS_PER_B, BB);    // (112, 16) = 1792 blocks
    lr_fused<<<grid, NT>>>(xs, ds, ilens, out);
}